// round 4
// baseline (speedup 1.0000x reference)
#include <cuda_runtime.h>
#include <stdint.h>

// SparseGather: out[m, i, j, c] = inputs[n_m, y0_m + i, x0_m + j, c]
// inputs: (N=4, H=512, W=512, C=64) fp32
// active_block_indices: (M=4096, 3) int32 -> (n, by, bx); y0 = by*16, x0 = bx*16
// out: (M, 16, 16, 64) fp32
//
// Units of float4 (C=64 -> 16 float4 per pixel):
//   C4   = 16
//   WC4  = 512 * 16 = 8192   (row stride, float4)
//   HWC4 = 512 * WC4         (image stride, float4)
// Work item = half-block (8 rows): read 8 x 4KB strided rows, write 32KB contig.
//
// R3: persistent grid (148 SMs x 8 CTAs = 1184 CTAs) + grid-stride loop over
// 2*M half-blocks -> no wave transitions, no tail wave; __ldcg reads (L2-only,
// no L1 allocate -- zero intra-SM reuse), __stcs streaming stores.

#define C4   16
#define WC4  (512 * C4)
#define HWC4 (512 * WC4)

#define PERSIST_CTAS (148 * 8)

__global__ __launch_bounds__(256) void sparse_gather_kernel(
    const float4* __restrict__ in,
    const int*    __restrict__ idx,
    float4*       __restrict__ out,
    int work_items)                       // 2*M half-blocks
{
    const int t = threadIdx.x;            // 0..255

    for (int b = blockIdx.x; b < work_items; b += gridDim.x) {
        const int m  = b >> 1;            // block index
        const int r0 = (b & 1) << 3;      // row offset: 0 or 8

        const int n  = idx[3 * m + 0];
        const int by = idx[3 * m + 1];
        const int bx = idx[3 * m + 2];

        const float4* src = in
            + (size_t)n * HWC4
            + (size_t)(by * 16 + r0) * WC4
            + (size_t)(bx * 16) * C4;

        float4* dst = out + (size_t)m * 4096 + (size_t)r0 * 256;

        // 8 rows; each row = 256 contiguous float4 on both sides.
        float4 v[8];
        #pragma unroll
        for (int r = 0; r < 8; ++r) {
            v[r] = __ldcg(&src[(size_t)r * WC4 + t]);   // L2-only read
        }
        #pragma unroll
        for (int r = 0; r < 8; ++r) {
            __stcs(&dst[r * 256 + t], v[r]);            // streaming store
        }
    }
}

extern "C" void kernel_launch(void* const* d_in, const int* in_sizes, int n_in,
                              void* d_out, int out_size)
{
    const float4* in  = (const float4*)d_in[0];
    const int*    idx = (const int*)d_in[2];   // active_block_indices
    float4*       out = (float4*)d_out;

    const int M = in_sizes[2] / 3;             // 4096
    const int work_items = 2 * M;

    int grid = PERSIST_CTAS;
    if (grid > work_items) grid = work_items;

    sparse_gather_kernel<<<grid, 256>>>(in, idx, out, work_items);
}

// round 5
// speedup vs baseline: 1.0266x; 1.0266x over previous
#include <cuda_runtime.h>
#include <stdint.h>

// SparseGather: out[m, i, j, c] = inputs[n_m, y0_m + i, x0_m + j, c]
// inputs: (N=4, H=512, W=512, C=64) fp32
// active_block_indices: (M=4096, 3) int32 -> (n, by, bx); y0 = by*16, x0 = bx*16
// out: (M, 16, 16, 64) fp32
//
// Units of float4 (C=64 -> 16 float4 per pixel):
//   C4   = 16
//   WC4  = 512 * 16 = 8192   (row stride, float4)
//   HWC4 = 512 * WC4         (image stride, float4)
//
// R5: quarter-block per CTA (4 rows), grid = 4*M = 16384, 256 threads.
//   - MLP_p1 = 4 front-batched LDG.128 -> lower cross-CTA L1tex-queue spread
//   - finer tail quantum at wave boundaries
//   - __ldcg reads (no L1 allocate; zero intra-SM reuse), __stcs stores
//     (evict-first: the 268 MB write stream must not evict reusable input).

#define C4   16
#define WC4  (512 * C4)
#define HWC4 (512 * WC4)

__global__ __launch_bounds__(256) void sparse_gather_kernel(
    const float4* __restrict__ in,
    const int*    __restrict__ idx,
    float4*       __restrict__ out)
{
    const int b  = blockIdx.x;     // 0 .. 4*M-1
    const int m  = b >> 2;         // block index
    const int r0 = (b & 3) << 2;   // row offset: 0, 4, 8, 12
    const int t  = threadIdx.x;    // 0..255

    const int n  = idx[3 * m + 0];
    const int by = idx[3 * m + 1];
    const int bx = idx[3 * m + 2];

    const float4* src = in
        + (size_t)n * HWC4
        + (size_t)(by * 16 + r0) * WC4
        + (size_t)(bx * 16) * C4;

    float4* dst = out + (size_t)m * 4096 + (size_t)r0 * 256;

    // 4 rows; each row = 256 contiguous float4 on both sides.
    float4 v[4];
    #pragma unroll
    for (int r = 0; r < 4; ++r) {
        v[r] = __ldcg(&src[(size_t)r * WC4 + t]);   // L2-only read
    }
    #pragma unroll
    for (int r = 0; r < 4; ++r) {
        __stcs(&dst[r * 256 + t], v[r]);            // streaming store
    }
}

extern "C" void kernel_launch(void* const* d_in, const int* in_sizes, int n_in,
                              void* d_out, int out_size)
{
    const float4* in  = (const float4*)d_in[0];
    const int*    idx = (const int*)d_in[2];   // active_block_indices
    float4*       out = (float4*)d_out;

    const int M = in_sizes[2] / 3;             // 4096

    sparse_gather_kernel<<<4 * M, 256>>>(in, idx, out);
}